// round 11
// baseline (speedup 1.0000x reference)
#include <cuda_runtime.h>
#include <math.h>

#define B_ 8
#define T_ 2048
#define C_ 1024
#define H_ 64

// Scratch for projections (device globals: allocation-free)
__device__ float g_q[B_ * T_ * H_];   // holds 8*q (logit scale folded in)
__device__ float g_k[B_ * T_ * H_];
__device__ float g_v[B_ * T_ * H_];

// ---------------------------------------------------------------------------
// Fused projection GEMM: for W = [Wk; 8*Wq; Wv] (192 rows),
// out[m][h] = sum_c x[m][c] * W[h][c].  M = 16384, N = 192, K = 1024.
// BM=128, BN=192, BK=32; 256 threads; micro-tile 8 rows x (3 x 4) cols.
// Register prefetch of the next k-tile hides global-load latency.
// 128 blocks -> exactly one per SM (one wave, balanced).
// ---------------------------------------------------------------------------
#define PM 128
#define PN 192
#define PKC 32
#define PSTR 36  // smem row stride (floats), float4-aligned

__global__ __launch_bounds__(256, 1)
void proj_kernel(const float* __restrict__ x,
                 const float* __restrict__ Wk,
                 const float* __restrict__ Wq,
                 const float* __restrict__ Wv)
{
    __shared__ float xs[PM][PSTR];   // 18.4 KB
    __shared__ float ws[PN][PSTR];   // 27.6 KB

    const int tid = threadIdx.x;
    const int ty = tid >> 4;      // rows ty*8 .. +7
    const int tx = tid & 15;      // per section: cols tx*4 .. +3
    const int row0 = blockIdx.x * PM;

    // --- precompute load slots ---
    // x tile: 128x32 = 1024 float4 -> 4 per thread
    int xr[4], xc[4];
#pragma unroll
    for (int i = 0; i < 4; i++) {
        int idx = tid + i * 256;
        xr[i] = idx >> 3;
        xc[i] = (idx & 7) << 2;
    }
    // W tile: 192x32 = 1536 float4 -> 6 per thread
    const float* wptr[6];
    float wsc[6];
    int wh[6], wc[6];
#pragma unroll
    for (int i = 0; i < 6; i++) {
        int idx = tid + i * 256;
        int h = idx >> 3;
        wh[i] = h;
        wc[i] = (idx & 7) << 2;
        if (h < 64)       { wptr[i] = Wk + (size_t)h * C_;         wsc[i] = 1.f; }
        else if (h < 128) { wptr[i] = Wq + (size_t)(h - 64) * C_;  wsc[i] = 8.f; }
        else              { wptr[i] = Wv + (size_t)(h - 128) * C_; wsc[i] = 1.f; }
    }

    float acc[8][3][4];
#pragma unroll
    for (int i = 0; i < 8; i++)
#pragma unroll
        for (int s = 0; s < 3; s++)
#pragma unroll
            for (int j = 0; j < 4; j++) acc[i][s][j] = 0.f;

    float4 rx[4], rw[6];
    // prime tile 0
#pragma unroll
    for (int i = 0; i < 4; i++)
        rx[i] = *(const float4*)(x + (size_t)(row0 + xr[i]) * C_ + xc[i]);
#pragma unroll
    for (int i = 0; i < 6; i++) {
        float4 v = *(const float4*)(wptr[i] + wc[i]);
        v.x *= wsc[i]; v.y *= wsc[i]; v.z *= wsc[i]; v.w *= wsc[i];
        rw[i] = v;
    }
#pragma unroll
    for (int i = 0; i < 4; i++) *(float4*)&xs[xr[i]][xc[i]] = rx[i];
#pragma unroll
    for (int i = 0; i < 6; i++) *(float4*)&ws[wh[i]][wc[i]] = rw[i];
    __syncthreads();

    const int NKT = C_ / PKC;  // 32
    for (int kt = 0; kt < NKT; kt++) {
        // prefetch next tile into registers (latency hidden by compute)
        if (kt + 1 < NKT) {
            int kn = (kt + 1) * PKC;
#pragma unroll
            for (int i = 0; i < 4; i++)
                rx[i] = *(const float4*)(x + (size_t)(row0 + xr[i]) * C_ + kn + xc[i]);
#pragma unroll
            for (int i = 0; i < 6; i++) {
                float4 v = *(const float4*)(wptr[i] + kn + wc[i]);
                v.x *= wsc[i]; v.y *= wsc[i]; v.z *= wsc[i]; v.w *= wsc[i];
                rw[i] = v;
            }
        }

        // compute on current smem tile
#pragma unroll
        for (int kk = 0; kk < PKC; kk += 4) {
            float4 a[8];
#pragma unroll
            for (int i = 0; i < 8; i++) a[i] = *(float4*)&xs[ty * 8 + i][kk];
#pragma unroll
            for (int s = 0; s < 3; s++) {
                float4 b[4];
#pragma unroll
                for (int j = 0; j < 4; j++)
                    b[j] = *(float4*)&ws[s * 64 + tx * 4 + j][kk];
#pragma unroll
                for (int i = 0; i < 8; i++)
#pragma unroll
                    for (int j = 0; j < 4; j++)
                        acc[i][s][j] += a[i].x * b[j].x + a[i].y * b[j].y +
                                        a[i].z * b[j].z + a[i].w * b[j].w;
            }
        }
        __syncthreads();
        if (kt + 1 < NKT) {
#pragma unroll
            for (int i = 0; i < 4; i++) *(float4*)&xs[xr[i]][xc[i]] = rx[i];
#pragma unroll
            for (int i = 0; i < 6; i++) *(float4*)&ws[wh[i]][wc[i]] = rw[i];
            __syncthreads();
        }
    }

    // epilogue
#pragma unroll
    for (int s = 0; s < 3; s++) {
        float* out = (s == 0) ? g_k : (s == 1) ? g_q : g_v;
#pragma unroll
        for (int i = 0; i < 8; i++) {
            float4 v = make_float4(acc[i][s][0], acc[i][s][1],
                                   acc[i][s][2], acc[i][s][3]);
            *(float4*)(out + (size_t)(row0 + ty * 8 + i) * H_ + tx * 4) = v;
        }
    }
}

// ---------------------------------------------------------------------------
// Flash attention (fp32, causal; logit scale already folded into g_q).
// BM=64 query rows, BN=64 keys, D=64.  Each block processes TWO q-tiles
// (qb and 31-qb) so every block does exactly 33 equal KV tiles: perfectly
// balanced across the 128 blocks (16 pairs x 8 batches), one wave on 148 SMs.
// 256 threads; micro-tile 4 rows x 4 cols; 16-lane half-warp row reductions.
// ---------------------------------------------------------------------------
#define BM 64
#define BN 64
#define SSTR 68  // smem row stride (floats)

#define ATTN_SMEM (4 * BM * SSTR * 4)   // qs + ks + vs + ps

__global__ __launch_bounds__(256, 1)
void attn_kernel(float* __restrict__ out)
{
    extern __shared__ float sm[];
    float* qs = sm;                    // BM x SSTR
    float* ks = qs + BM * SSTR;        // BN x SSTR
    float* vs = ks + BN * SSTR;        // BN x SSTR
    float* ps = vs + BN * SSTR;        // BM x SSTR

    const int tid = threadIdx.x;
    const int ty = tid >> 4;           // rows ty*4 .. +3
    const int tx = tid & 15;           // cols tx*4 .. +3
    const int b  = blockIdx.y;

    const float* qg = g_q + (size_t)b * T_ * H_;
    const float* kg = g_k + (size_t)b * T_ * H_;
    const float* vg = g_v + (size_t)b * T_ * H_;

    const int NQB = T_ / BM;           // 32

#pragma unroll 1
    for (int pass = 0; pass < 2; pass++) {
        const int qb = pass ? (NQB - 1 - (int)blockIdx.x) : (int)blockIdx.x;
        const int q0 = qb * BM;

        __syncthreads();               // protect smem reuse across passes
        // Load Q tile (already scaled by 8): 64x64 = 1024 float4 -> 4/thread
#pragma unroll
        for (int i = 0; i < 4; i++) {
            int idx = tid + i * 256;
            int r = idx >> 4, c = (idx & 15) << 2;
            *(float4*)&qs[r * SSTR + c] =
                *(const float4*)(qg + (size_t)(q0 + r) * H_ + c);
        }

        float m[4], l[4], o[4][4];
#pragma unroll
        for (int i = 0; i < 4; i++) {
            m[i] = -1e30f; l[i] = 0.f;
#pragma unroll
            for (int j = 0; j < 4; j++) o[i][j] = 0.f;
        }

        const int ntiles = qb + 1;     // causal: KV tiles 0..qb

        for (int kb = 0; kb < ntiles; kb++) {
            __syncthreads();           // ks/vs/ps reuse
            const int key0 = kb * BN;
            // K and V tiles: 64x64 each = 1024 float4 each -> 4+4 per thread
#pragma unroll
            for (int i = 0; i < 4; i++) {
                int idx = tid + i * 256;
                int r = idx >> 4, c = (idx & 15) << 2;
                *(float4*)&ks[r * SSTR + c] =
                    *(const float4*)(kg + (size_t)(key0 + r) * H_ + c);
                *(float4*)&vs[r * SSTR + c] =
                    *(const float4*)(vg + (size_t)(key0 + r) * H_ + c);
            }
            __syncthreads();

            // S = Q_tile @ K_tile^T
            float s[4][4];
#pragma unroll
            for (int i = 0; i < 4; i++)
#pragma unroll
                for (int j = 0; j < 4; j++) s[i][j] = 0.f;

#pragma unroll
            for (int d = 0; d < H_; d += 4) {
                float4 a[4], bb[4];
#pragma unroll
                for (int i = 0; i < 4; i++)
                    a[i] = *(float4*)&qs[(ty * 4 + i) * SSTR + d];
#pragma unroll
                for (int j = 0; j < 4; j++)
                    bb[j] = *(float4*)&ks[(tx * 4 + j) * SSTR + d];
#pragma unroll
                for (int i = 0; i < 4; i++)
#pragma unroll
                    for (int j = 0; j < 4; j++)
                        s[i][j] += a[i].x * bb[j].x + a[i].y * bb[j].y +
                                   a[i].z * bb[j].z + a[i].w * bb[j].w;
            }

            // causal mask: only the diagonal tile needs it
            if (kb == qb) {
#pragma unroll
                for (int i = 0; i < 4; i++)
#pragma unroll
                    for (int j = 0; j < 4; j++)
                        if (key0 + tx * 4 + j > q0 + ty * 4 + i)
                            s[i][j] = -1e30f;
            }

            // online softmax (per row; 16-lane half-warp reductions)
#pragma unroll
            for (int i = 0; i < 4; i++) {
                float mx = fmaxf(fmaxf(s[i][0], s[i][1]),
                                 fmaxf(s[i][2], s[i][3]));
#pragma unroll
                for (int off = 8; off >= 1; off >>= 1)
                    mx = fmaxf(mx, __shfl_xor_sync(0xffffffffu, mx, off));
                float mn = fmaxf(m[i], mx);
                float corr = __expf(m[i] - mn);
                float p0 = __expf(s[i][0] - mn);
                float p1 = __expf(s[i][1] - mn);
                float p2 = __expf(s[i][2] - mn);
                float p3 = __expf(s[i][3] - mn);
                float sum = p0 + p1 + p2 + p3;
#pragma unroll
                for (int off = 8; off >= 1; off >>= 1)
                    sum += __shfl_xor_sync(0xffffffffu, sum, off);
                l[i] = l[i] * corr + sum;
                m[i] = mn;
                o[i][0] *= corr; o[i][1] *= corr;
                o[i][2] *= corr; o[i][3] *= corr;
                *(float4*)&ps[(ty * 4 + i) * SSTR + tx * 4] =
                    make_float4(p0, p1, p2, p3);
            }
            __syncthreads();

            // O += P @ V
#pragma unroll
            for (int s0 = 0; s0 < BN; s0 += 4) {
                float4 pa[4], vb[4];
#pragma unroll
                for (int i = 0; i < 4; i++)
                    pa[i] = *(float4*)&ps[(ty * 4 + i) * SSTR + s0];
#pragma unroll
                for (int k = 0; k < 4; k++)
                    vb[k] = *(float4*)&vs[(s0 + k) * SSTR + tx * 4];
#pragma unroll
                for (int i = 0; i < 4; i++) {
                    o[i][0] += pa[i].x * vb[0].x + pa[i].y * vb[1].x +
                               pa[i].z * vb[2].x + pa[i].w * vb[3].x;
                    o[i][1] += pa[i].x * vb[0].y + pa[i].y * vb[1].y +
                               pa[i].z * vb[2].y + pa[i].w * vb[3].y;
                    o[i][2] += pa[i].x * vb[0].z + pa[i].y * vb[1].z +
                               pa[i].z * vb[2].z + pa[i].w * vb[3].z;
                    o[i][3] += pa[i].x * vb[0].w + pa[i].y * vb[1].w +
                               pa[i].z * vb[2].w + pa[i].w * vb[3].w;
                }
            }
        }

        // epilogue: divide by row sums, write [B,T,H]
#pragma unroll
        for (int i = 0; i < 4; i++) {
            float inv = 1.f / l[i];
            float4 v = make_float4(o[i][0] * inv, o[i][1] * inv,
                                   o[i][2] * inv, o[i][3] * inv);
            *(float4*)(out + ((size_t)b * T_ + q0 + ty * 4 + i) * H_ + tx * 4) = v;
        }
    }
}

// ---------------------------------------------------------------------------
extern "C" void kernel_launch(void* const* d_in, const int* in_sizes, int n_in,
                              void* d_out, int out_size)
{
    const float* x  = (const float*)d_in[0];
    const float* Wk = (const float*)d_in[1];
    const float* Wq = (const float*)d_in[2];
    const float* Wv = (const float*)d_in[3];
    float* out = (float*)d_out;

    (void)in_sizes; (void)n_in; (void)out_size;

    cudaFuncSetAttribute(attn_kernel,
                         cudaFuncAttributeMaxDynamicSharedMemorySize,
                         ATTN_SMEM);

    dim3 pgrid((B_ * T_) / PM, 1);
    proj_kernel<<<pgrid, 256>>>(x, Wk, Wq, Wv);

    dim3 agrid((T_ / BM) / 2, B_);   // 16 balanced pairs x 8 batches
    attn_kernel<<<agrid, 256, ATTN_SMEM>>>(out);
}

// round 12
// speedup vs baseline: 1.4539x; 1.4539x over previous
#include <cuda_runtime.h>
#include <math.h>

#define B_ 8
#define T_ 2048
#define C_ 1024
#define H_ 64

// Scratch (device globals: allocation-free)
__device__ float g_q[B_ * T_ * H_];     // 8*q (logit scale folded into Wq)
__device__ float g_k[B_ * T_ * H_];
__device__ float g_v[B_ * T_ * H_];
__device__ float g_kt[B_ * H_ * T_];    // K transposed per batch: [b][d][t]
__device__ float g_wt[C_ * 192];        // fused W transposed: [c][h], h=0..191

// ---------------------------------------------------------------------------
// One-shot transpose of [Wk; 8*Wq; Wv] (192 x 1024) -> g_wt (1024 x 192)
// ---------------------------------------------------------------------------
__global__ void wtrans_kernel(const float* __restrict__ Wk,
                              const float* __restrict__ Wq,
                              const float* __restrict__ Wv)
{
    __shared__ float tile[32][33];
    const int h0 = blockIdx.y * 32, c0 = blockIdx.x * 32;
    const int h = h0 + threadIdx.y;
    const float* W; float sc = 1.f;
    if (h < 64)        W = Wk + (size_t)h * C_;
    else if (h < 128) { W = Wq + (size_t)(h - 64) * C_; sc = 8.f; }
    else               W = Wv + (size_t)(h - 128) * C_;
    tile[threadIdx.y][threadIdx.x] = W[c0 + threadIdx.x] * sc;
    __syncthreads();
    g_wt[(size_t)(c0 + threadIdx.y) * 192 + h0 + threadIdx.x] =
        tile[threadIdx.x][threadIdx.y];
}

// ---------------------------------------------------------------------------
// One-shot transpose of g_k [b][t][h] -> g_kt [b][h][t]
// ---------------------------------------------------------------------------
__global__ void ktrans_kernel()
{
    __shared__ float tile[32][33];
    const int b = blockIdx.z, h0 = blockIdx.y * 32, t0 = blockIdx.x * 32;
    const float* src = g_k + (size_t)b * T_ * H_;
    float* dst = g_kt + (size_t)b * H_ * T_;
    tile[threadIdx.y][threadIdx.x] =
        src[(size_t)(t0 + threadIdx.y) * H_ + h0 + threadIdx.x];
    __syncthreads();
    dst[(size_t)(h0 + threadIdx.y) * T_ + t0 + threadIdx.x] =
        tile[threadIdx.x][threadIdx.y];
}

// ---------------------------------------------------------------------------
// Fused projection GEMM (W pre-transposed in g_wt -> conflict-free operand
// loads: inner dim k indexes smem ROWS).
// M=16384, N=192, K=1024. BM=128, BK=32, 256 threads, micro 8 x (3x4).
// ---------------------------------------------------------------------------
#define PM 128
#define PKC 32
#define PSTR 36
#define WSTR 200

__global__ __launch_bounds__(256, 1)
void proj_kernel(const float* __restrict__ x)
{
    __shared__ float xs[PM][PSTR];   // x tile, row-major [m][k]
    __shared__ float wt[PKC][WSTR];  // W tile, transposed [k][h]

    const int tid = threadIdx.x;
    const int ty = tid >> 4;
    const int tx = tid & 15;
    const int row0 = blockIdx.x * PM;

    // x slots: 1024 float4 -> 4/thread
    int xr[4], xc[4];
#pragma unroll
    for (int i = 0; i < 4; i++) {
        int idx = tid + i * 256;
        xr[i] = idx >> 3;
        xc[i] = (idx & 7) << 2;
    }
    // wt slots: 32 rows x 192 cols = 1536 float4 -> 6/thread
    int wr[6], wc[6];
#pragma unroll
    for (int i = 0; i < 6; i++) {
        int idx = tid + i * 256;
        wr[i] = idx / 48;
        wc[i] = (idx % 48) * 4;
    }

    float acc[8][3][4];
#pragma unroll
    for (int i = 0; i < 8; i++)
#pragma unroll
        for (int s = 0; s < 3; s++)
#pragma unroll
            for (int j = 0; j < 4; j++) acc[i][s][j] = 0.f;

    float4 rx[4], rw[6];
    // prime k-tile 0
#pragma unroll
    for (int i = 0; i < 4; i++)
        rx[i] = *(const float4*)(x + (size_t)(row0 + xr[i]) * C_ + xc[i]);
#pragma unroll
    for (int i = 0; i < 6; i++)
        rw[i] = *(const float4*)(g_wt + (size_t)wr[i] * 192 + wc[i]);
#pragma unroll
    for (int i = 0; i < 4; i++) *(float4*)&xs[xr[i]][xc[i]] = rx[i];
#pragma unroll
    for (int i = 0; i < 6; i++) *(float4*)&wt[wr[i]][wc[i]] = rw[i];
    __syncthreads();

    const int NKT = C_ / PKC;
    for (int kt = 0; kt < NKT; kt++) {
        if (kt + 1 < NKT) {
            int kn = (kt + 1) * PKC;
#pragma unroll
            for (int i = 0; i < 4; i++)
                rx[i] = *(const float4*)(x + (size_t)(row0 + xr[i]) * C_ + kn + xc[i]);
#pragma unroll
            for (int i = 0; i < 6; i++)
                rw[i] = *(const float4*)(g_wt + (size_t)(kn + wr[i]) * 192 + wc[i]);
        }

#pragma unroll
        for (int kk = 0; kk < PKC; kk += 4) {
            float4 a[8];
#pragma unroll
            for (int i = 0; i < 8; i++) a[i] = *(float4*)&xs[ty * 8 + i][kk];
#pragma unroll
            for (int s = 0; s < 3; s++) {
                float4 b0 = *(float4*)&wt[kk + 0][s * 64 + tx * 4];
                float4 b1 = *(float4*)&wt[kk + 1][s * 64 + tx * 4];
                float4 b2 = *(float4*)&wt[kk + 2][s * 64 + tx * 4];
                float4 b3 = *(float4*)&wt[kk + 3][s * 64 + tx * 4];
#pragma unroll
                for (int i = 0; i < 8; i++) {
                    acc[i][s][0] += a[i].x * b0.x + a[i].y * b1.x +
                                    a[i].z * b2.x + a[i].w * b3.x;
                    acc[i][s][1] += a[i].x * b0.y + a[i].y * b1.y +
                                    a[i].z * b2.y + a[i].w * b3.y;
                    acc[i][s][2] += a[i].x * b0.z + a[i].y * b1.z +
                                    a[i].z * b2.z + a[i].w * b3.z;
                    acc[i][s][3] += a[i].x * b0.w + a[i].y * b1.w +
                                    a[i].z * b2.w + a[i].w * b3.w;
                }
            }
        }
        __syncthreads();
        if (kt + 1 < NKT) {
#pragma unroll
            for (int i = 0; i < 4; i++) *(float4*)&xs[xr[i]][xc[i]] = rx[i];
#pragma unroll
            for (int i = 0; i < 6; i++) *(float4*)&wt[wr[i]][wc[i]] = rw[i];
            __syncthreads();
        }
    }

#pragma unroll
    for (int s = 0; s < 3; s++) {
        float* out = (s == 0) ? g_k : (s == 1) ? g_q : g_v;
#pragma unroll
        for (int i = 0; i < 8; i++) {
            float4 v = make_float4(acc[i][s][0], acc[i][s][1],
                                   acc[i][s][2], acc[i][s][3]);
            *(float4*)(out + (size_t)(row0 + ty * 8 + i) * H_ + tx * 4) = v;
        }
    }
}

// ---------------------------------------------------------------------------
// Flash attention (fp32, causal, scale pre-folded). BM=BN=64.
// K tile held TRANSPOSED in smem (kt[d][key]) -> conflict-free QK^T loads.
// Double-buffered KV smem pipeline hides global-load latency.
// Block processes q-tiles (j, 31-j): 33 equal KV tiles per block, 128 blocks.
// ---------------------------------------------------------------------------
#define BM 64
#define BN 64
#define SSTR 68
#define KSTR 68

// qs + ps + 2*kt + 2*vs
#define ATTN_SMEM ((2 * BM * SSTR + 4 * BN * KSTR) * 4)

__global__ __launch_bounds__(256, 1)
void attn_kernel(float* __restrict__ out)
{
    extern __shared__ float sm[];
    float* qs  = sm;                         // [64][SSTR]
    float* ps  = qs + BM * SSTR;             // [64][SSTR]
    float* ktb = ps + BM * SSTR;             // 2 x [64][KSTR]  (kt[d][key])
    float* vsb = ktb + 2 * BN * KSTR;        // 2 x [64][KSTR]  (v[key][d])

    const int tid = threadIdx.x;
    const int ty = tid >> 4;
    const int tx = tid & 15;
    const int b  = blockIdx.y;

    const float* qg  = g_q  + (size_t)b * T_ * H_;
    const float* ktg = g_kt + (size_t)b * H_ * T_;
    const float* vg  = g_v  + (size_t)b * T_ * H_;

    // load slots for KV tiles: 1024 float4 each -> 4/thread each
    int lr[4], lc[4];
#pragma unroll
    for (int i = 0; i < 4; i++) {
        int idx = tid + i * 256;
        lr[i] = idx >> 4;
        lc[i] = (idx & 15) << 2;
    }

    const int NQB = T_ / BM;   // 32

#pragma unroll 1
    for (int pass = 0; pass < 2; pass++) {
        const int qb = pass ? (NQB - 1 - (int)blockIdx.x) : (int)blockIdx.x;
        const int q0 = qb * BM;
        const int ntiles = qb + 1;

        __syncthreads();  // smem reuse across passes
        // Q tile (already scaled): row-major
#pragma unroll
        for (int i = 0; i < 4; i++)
            *(float4*)&qs[lr[i] * SSTR + lc[i]] =
                *(const float4*)(qg + (size_t)(q0 + lr[i]) * H_ + lc[i]);

        // preload KV tile 0 into buffer 0
        {
            float4 rk[4], rv[4];
#pragma unroll
            for (int i = 0; i < 4; i++) {
                rk[i] = *(const float4*)(ktg + (size_t)lr[i] * T_ + lc[i]);
                rv[i] = *(const float4*)(vg  + (size_t)lr[i] * H_ + lc[i]);
            }
#pragma unroll
            for (int i = 0; i < 4; i++) {
                *(float4*)&ktb[lr[i] * KSTR + lc[i]] = rk[i];
                *(float4*)&vsb[lr[i] * KSTR + lc[i]] = rv[i];
            }
        }

        float m[4], l[4], o[4][4];
#pragma unroll
        for (int i = 0; i < 4; i++) {
            m[i] = -1e30f; l[i] = 0.f;
#pragma unroll
            for (int j = 0; j < 4; j++) o[i][j] = 0.f;
        }

        __syncthreads();  // buffer 0 + qs ready

        for (int kb = 0; kb < ntiles; kb++) {
            const int cur = kb & 1;
            const int key0 = kb * BN;
            float* kt = ktb + cur * BN * KSTR;
            float* vs = vsb + cur * BN * KSTR;

            // issue next tile's global loads early (latency hidden by QK)
            float4 rk[4], rv[4];
            const bool more = (kb + 1 < ntiles);
            if (more) {
                const int nkey0 = key0 + BN;
#pragma unroll
                for (int i = 0; i < 4; i++) {
                    rk[i] = *(const float4*)(ktg + (size_t)lr[i] * T_ + nkey0 + lc[i]);
                    rv[i] = *(const float4*)(vg + (size_t)(nkey0 + lr[i]) * H_ + lc[i]);
                }
            }

            // S = Q @ K^T  (kt rows = d -> conflict-free operand loads)
            float s[4][4];
#pragma unroll
            for (int i = 0; i < 4; i++)
#pragma unroll
                for (int j = 0; j < 4; j++) s[i][j] = 0.f;

#pragma unroll
            for (int d = 0; d < H_; d += 4) {
                float4 a[4];
#pragma unroll
                for (int i = 0; i < 4; i++)
                    a[i] = *(float4*)&qs[(ty * 4 + i) * SSTR + d];
                float4 b0 = *(float4*)&kt[(d + 0) * KSTR + tx * 4];
                float4 b1 = *(float4*)&kt[(d + 1) * KSTR + tx * 4];
                float4 b2 = *(float4*)&kt[(d + 2) * KSTR + tx * 4];
                float4 b3 = *(float4*)&kt[(d + 3) * KSTR + tx * 4];
#pragma unroll
                for (int i = 0; i < 4; i++) {
                    s[i][0] += a[i].x * b0.x + a[i].y * b1.x +
                               a[i].z * b2.x + a[i].w * b3.x;
                    s[i][1] += a[i].x * b0.y + a[i].y * b1.y +
                               a[i].z * b2.y + a[i].w * b3.y;
                    s[i][2] += a[i].x * b0.z + a[i].y * b1.z +
                               a[i].z * b2.z + a[i].w * b3.z;
                    s[i][3] += a[i].x * b0.w + a[i].y * b1.w +
                               a[i].z * b2.w + a[i].w * b3.w;
                }
            }

            if (kb == qb) {  // diagonal tile: causal mask
#pragma unroll
                for (int i = 0; i < 4; i++)
#pragma unroll
                    for (int j = 0; j < 4; j++)
                        if (key0 + tx * 4 + j > q0 + ty * 4 + i)
                            s[i][j] = -1e30f;
            }

            // online softmax
#pragma unroll
            for (int i = 0; i < 4; i++) {
                float mx = fmaxf(fmaxf(s[i][0], s[i][1]),
                                 fmaxf(s[i][2], s[i][3]));
#pragma unroll
                for (int off = 8; off >= 1; off >>= 1)
                    mx = fmaxf(mx, __shfl_xor_sync(0xffffffffu, mx, off));
                float mn = fmaxf(m[i], mx);
                float corr = __expf(m[i] - mn);
                float p0 = __expf(s[i][0] - mn);
                float p1 = __expf(s[i][1] - mn);
                float p2 = __expf(s[i][2] - mn);
                float p3 = __expf(s[i][3] - mn);
                float sum = p0 + p1 + p2 + p3;
#pragma unroll
                for (int off = 8; off >= 1; off >>= 1)
                    sum += __shfl_xor_sync(0xffffffffu, sum, off);
                l[i] = l[i] * corr + sum;
                m[i] = mn;
                o[i][0] *= corr; o[i][1] *= corr;
                o[i][2] *= corr; o[i][3] *= corr;
                *(float4*)&ps[(ty * 4 + i) * SSTR + tx * 4] =
                    make_float4(p0, p1, p2, p3);
            }
            __syncthreads();  // ps ready; kt[cur] reads done

            // O += P @ V
#pragma unroll
            for (int s0 = 0; s0 < BN; s0 += 4) {
                float4 pa[4];
#pragma unroll
                for (int i = 0; i < 4; i++)
                    pa[i] = *(float4*)&ps[(ty * 4 + i) * SSTR + s0];
                float4 v0 = *(float4*)&vs[(s0 + 0) * KSTR + tx * 4];
                float4 v1 = *(float4*)&vs[(s0 + 1) * KSTR + tx * 4];
                float4 v2 = *(float4*)&vs[(s0 + 2) * KSTR + tx * 4];
                float4 v3 = *(float4*)&vs[(s0 + 3) * KSTR + tx * 4];
#pragma unroll
                for (int i = 0; i < 4; i++) {
                    o[i][0] += pa[i].x * v0.x + pa[i].y * v1.x +
                               pa[i].z * v2.x + pa[i].w * v3.x;
                    o[i][1] += pa[i].x * v0.y + pa[i].y * v1.y +
                               pa[i].z * v2.y + pa[i].w * v3.y;
                    o[i][2] += pa[i].x * v0.z + pa[i].y * v1.z +
                               pa[i].z * v2.z + pa[i].w * v3.z;
                    o[i][3] += pa[i].x * v0.w + pa[i].y * v1.w +
                               pa[i].z * v2.w + pa[i].w * v3.w;
                }
            }

            if (more) {  // stage next tile into the other buffer
                float* ktn = ktb + (cur ^ 1) * BN * KSTR;
                float* vsn = vsb + (cur ^ 1) * BN * KSTR;
#pragma unroll
                for (int i = 0; i < 4; i++) {
                    *(float4*)&ktn[lr[i] * KSTR + lc[i]] = rk[i];
                    *(float4*)&vsn[lr[i] * KSTR + lc[i]] = rv[i];
                }
            }
            __syncthreads();  // next buffer ready; ps/vs consumed
        }

        // epilogue
#pragma unroll
        for (int i = 0; i < 4; i++) {
            float inv = 1.f / l[i];
            float4 v = make_float4(o[i][0] * inv, o[i][1] * inv,
                                   o[i][2] * inv, o[i][3] * inv);
            *(float4*)(out + ((size_t)b * T_ + q0 + ty * 4 + i) * H_ + tx * 4) = v;
        }
    }
}

// ---------------------------------------------------------------------------
extern "C" void kernel_launch(void* const* d_in, const int* in_sizes, int n_in,
                              void* d_out, int out_size)
{
    const float* x  = (const float*)d_in[0];
    const float* Wk = (const float*)d_in[1];
    const float* Wq = (const float*)d_in[2];
    const float* Wv = (const float*)d_in[3];
    float* out = (float*)d_out;

    (void)in_sizes; (void)n_in; (void)out_size;

    cudaFuncSetAttribute(attn_kernel,
                         cudaFuncAttributeMaxDynamicSharedMemorySize,
                         ATTN_SMEM);

    dim3 wgrid(C_ / 32, 6);
    wtrans_kernel<<<wgrid, dim3(32, 32)>>>(Wk, Wq, Wv);

    dim3 pgrid((B_ * T_) / PM, 1);
    proj_kernel<<<pgrid, 256>>>(x);

    dim3 kgrid(T_ / 32, H_ / 32, B_);
    ktrans_kernel<<<kgrid, dim3(32, 32)>>>();

    dim3 agrid((T_ / BM) / 2, B_);
    attn_kernel<<<agrid, 256, ATTN_SMEM>>>(out);
}

// round 14
// speedup vs baseline: 2.2388x; 1.5399x over previous
#include <cuda_runtime.h>
#include <cuda_bf16.h>
#include <math.h>
#include <stdint.h>

#define B_ 8
#define T_ 2048
#define C_ 1024
#define H_ 64

// Scratch (device globals: allocation-free)
__device__ float g_q[B_ * T_ * H_];     // 8*q (logit scale folded into Wq)
__device__ float g_k[B_ * T_ * H_];
__device__ float g_v[B_ * T_ * H_];
__device__ float g_kt[B_ * H_ * T_];    // K transposed per batch: [b][d][t]

// ===========================================================================
// Warp-level tensor core helpers (sm_80+ features: compile for plain sm_103)
// ===========================================================================
__device__ __forceinline__ uint32_t smem_u32(const void* p) {
    uint32_t a;
    asm("{ .reg .u64 t; cvta.to.shared.u64 t, %1; cvt.u32.u64 %0, t; }"
        : "=r"(a) : "l"(p));
    return a;
}

#define LDSM4(r0, r1, r2, r3, addr) \
    asm volatile("ldmatrix.sync.aligned.m8n8.x4.shared.b16 {%0,%1,%2,%3}, [%4];" \
                 : "=r"(r0), "=r"(r1), "=r"(r2), "=r"(r3) : "r"(addr))
#define LDSM2(r0, r1, addr) \
    asm volatile("ldmatrix.sync.aligned.m8n8.x2.shared.b16 {%0,%1}, [%2];" \
                 : "=r"(r0), "=r"(r1) : "r"(addr))

__device__ __forceinline__ void mma16816(float* c,
                                         uint32_t a0, uint32_t a1,
                                         uint32_t a2, uint32_t a3,
                                         uint32_t b0, uint32_t b1) {
    asm volatile(
        "mma.sync.aligned.m16n8k16.row.col.f32.bf16.bf16.f32 "
        "{%0,%1,%2,%3}, {%4,%5,%6,%7}, {%8,%9}, {%0,%1,%2,%3};"
        : "+f"(c[0]), "+f"(c[1]), "+f"(c[2]), "+f"(c[3])
        : "r"(a0), "r"(a1), "r"(a2), "r"(a3), "r"(b0), "r"(b1));
}

// split one float4 into hi/lo bf16x4 (packed as uint2 each)
__device__ __forceinline__ void bf16_split4(float4 v, uint2& hv, uint2& lv) {
    __nv_bfloat16 h0 = __float2bfloat16_rn(v.x);
    __nv_bfloat16 h1 = __float2bfloat16_rn(v.y);
    __nv_bfloat16 h2 = __float2bfloat16_rn(v.z);
    __nv_bfloat16 h3 = __float2bfloat16_rn(v.w);
    __nv_bfloat16 l0 = __float2bfloat16_rn(v.x - __bfloat162float(h0));
    __nv_bfloat16 l1 = __float2bfloat16_rn(v.y - __bfloat162float(h1));
    __nv_bfloat16 l2 = __float2bfloat16_rn(v.z - __bfloat162float(h2));
    __nv_bfloat16 l3 = __float2bfloat16_rn(v.w - __bfloat162float(h3));
    hv.x = (uint32_t)__bfloat16_as_ushort(h0) |
           ((uint32_t)__bfloat16_as_ushort(h1) << 16);
    hv.y = (uint32_t)__bfloat16_as_ushort(h2) |
           ((uint32_t)__bfloat16_as_ushort(h3) << 16);
    lv.x = (uint32_t)__bfloat16_as_ushort(l0) |
           ((uint32_t)__bfloat16_as_ushort(l1) << 16);
    lv.y = (uint32_t)__bfloat16_as_ushort(l2) |
           ((uint32_t)__bfloat16_as_ushort(l3) << 16);
}

// ---------------------------------------------------------------------------
// Tensor-core projection GEMM (mma.sync bf16 hi/lo split, 3 MMAs per pair):
//   out[m][h] = sum_c x[m][c] * W[h][c],  M=16384, N=192, K=1024.
// Block: 128 M x 192 N, 256 threads = 8 warps (4 x 2), warp tile 32 x 96.
// BK=32, double-buffered smem, 40-bf16 (80 B) row stride -> conflict-free
// ldmatrix (rows*80 mod 128 all distinct multiples of 16).
// ---------------------------------------------------------------------------
#define PSTRB 40                         // smem row stride in bf16 (80 bytes)
#define BUF_ELE (320 * PSTRB * 2)        // (128 A + 192 B rows) * hi+lo
#define AH_OFF 0
#define AL_OFF (128 * PSTRB)
#define BH_OFF (256 * PSTRB)
#define BL_OFF (448 * PSTRB)
#define PROJ_SMEM (2 * BUF_ELE * 2)      // bytes = 102400

__global__ __launch_bounds__(256, 1)
void proj_kernel(const float* __restrict__ x,
                 const float* __restrict__ Wk,
                 const float* __restrict__ Wq,
                 const float* __restrict__ Wv)
{
    extern __shared__ __align__(16) char smem[];
    __nv_bfloat16* sb16 = (__nv_bfloat16*)smem;
    const uint32_t sb = smem_u32(smem);

    const int tid = threadIdx.x;
    const int wid = tid >> 5;
    const int lane = tid & 31;
    const int row0 = blockIdx.x * 128;
    const int warp_m = (wid >> 1) * 32;   // 0,32,64,96
    const int warp_n = (wid & 1) * 96;    // 0,96

    // --- global load slots ---
    // A: 128 rows x 32 floats = 1024 float4 -> 4/thread
    int ar[4], ac[4];
#pragma unroll
    for (int i = 0; i < 4; i++) {
        int idx = tid + i * 256;
        ar[i] = idx >> 3;
        ac[i] = (idx & 7) << 2;
    }
    // B: 192 rows x 32 floats = 1536 float4 -> 6/thread
    const float* wp[6];
    float wsc[6];
    int wr[6], wc[6];
#pragma unroll
    for (int i = 0; i < 6; i++) {
        int idx = tid + i * 256;
        int r = idx >> 3;
        wr[i] = r;
        wc[i] = (idx & 7) << 2;
        if (r < 64)       { wp[i] = Wk + (size_t)r * C_;         wsc[i] = 1.f; }
        else if (r < 128) { wp[i] = Wq + (size_t)(r - 64) * C_;  wsc[i] = 8.f; }
        else              { wp[i] = Wv + (size_t)(r - 128) * C_; wsc[i] = 1.f; }
    }

    // --- ldmatrix lane address components (bytes, within buffer) ---
    // A x4: lanes 0-15 -> rows 0-15 (k0), lanes 16-31 -> rows 0-15 (k+8)
    const uint32_t a_lrow = (uint32_t)(lane & 15);
    const uint32_t a_koff = (uint32_t)((lane >> 4) * 16);   // bytes
    // B x2: lanes 0-7 -> n rows (k0), lanes 8-15 -> n rows (k+8)
    const uint32_t b_lrow = (uint32_t)(lane & 7);
    const uint32_t b_koff = (uint32_t)(((lane >> 3) & 1) * 16);

    float acc[2][12][4];
#pragma unroll
    for (int mi = 0; mi < 2; mi++)
#pragma unroll
        for (int nj = 0; nj < 12; nj++)
#pragma unroll
            for (int q = 0; q < 4; q++) acc[mi][nj][q] = 0.f;

    // --- prime buffer 0 ---
    {
        __nv_bfloat16* base = sb16;
#pragma unroll
        for (int i = 0; i < 4; i++) {
            float4 v = *(const float4*)(x + (size_t)(row0 + ar[i]) * C_ + ac[i]);
            uint2 hv, lv; bf16_split4(v, hv, lv);
            int off = ar[i] * PSTRB + ac[i];
            *(uint2*)(base + AH_OFF + off) = hv;
            *(uint2*)(base + AL_OFF + off) = lv;
        }
#pragma unroll
        for (int i = 0; i < 6; i++) {
            float4 v = *(const float4*)(wp[i] + wc[i]);
            v.x *= wsc[i]; v.y *= wsc[i]; v.z *= wsc[i]; v.w *= wsc[i];
            uint2 hv, lv; bf16_split4(v, hv, lv);
            int off = wr[i] * PSTRB + wc[i];
            *(uint2*)(base + BH_OFF + off) = hv;
            *(uint2*)(base + BL_OFF + off) = lv;
        }
    }
    __syncthreads();

    const int NKT = C_ / 32;   // 32
    for (int kt = 0; kt < NKT; kt++) {
        const int cur = kt & 1;
        const bool more = (kt + 1 < NKT);

        // prefetch next k-tile into registers
        float4 rxa[4], rxb[6];
        if (more) {
            const int kc = (kt + 1) * 32;
#pragma unroll
            for (int i = 0; i < 4; i++)
                rxa[i] = *(const float4*)(x + (size_t)(row0 + ar[i]) * C_ + kc + ac[i]);
#pragma unroll
            for (int i = 0; i < 6; i++) {
                float4 v = *(const float4*)(wp[i] + kc + wc[i]);
                v.x *= wsc[i]; v.y *= wsc[i]; v.z *= wsc[i]; v.w *= wsc[i];
                rxb[i] = v;
            }
        }

        // MMA over the current buffer (2 k-steps of 16)
        const uint32_t bufb = sb + cur * BUF_ELE * 2;   // byte base
#pragma unroll
        for (int ks = 0; ks < 2; ks++) {
            const uint32_t kb = ks * 32;                 // 16 bf16 = 32 bytes
            uint32_t ah[2][4], al[2][4];
#pragma unroll
            for (int mi = 0; mi < 2; mi++) {
                uint32_t rowa = warp_m + mi * 16 + a_lrow;
                uint32_t aaddr = bufb + AH_OFF * 2 + rowa * (PSTRB * 2) +
                                 a_koff + kb;
                LDSM4(ah[mi][0], ah[mi][1], ah[mi][2], ah[mi][3], aaddr);
                uint32_t laddr = aaddr + (AL_OFF - AH_OFF) * 2;
                LDSM4(al[mi][0], al[mi][1], al[mi][2], al[mi][3], laddr);
            }
#pragma unroll
            for (int nj = 0; nj < 12; nj++) {
                uint32_t rowb = warp_n + nj * 8 + b_lrow;
                uint32_t baddr = bufb + BH_OFF * 2 + rowb * (PSTRB * 2) +
                                 b_koff + kb;
                uint32_t bh0, bh1, bl0, bl1;
                LDSM2(bh0, bh1, baddr);
                LDSM2(bl0, bl1, baddr + (BL_OFF - BH_OFF) * 2);
#pragma unroll
                for (int mi = 0; mi < 2; mi++) {
                    mma16816(acc[mi][nj], ah[mi][0], ah[mi][1], ah[mi][2],
                             ah[mi][3], bh0, bh1);
                    mma16816(acc[mi][nj], ah[mi][0], ah[mi][1], ah[mi][2],
                             ah[mi][3], bl0, bl1);
                    mma16816(acc[mi][nj], al[mi][0], al[mi][1], al[mi][2],
                             al[mi][3], bh0, bh1);
                }
            }
        }

        // store prefetched tile into the other buffer
        if (more) {
            __nv_bfloat16* base = sb16 + (cur ^ 1) * BUF_ELE;
#pragma unroll
            for (int i = 0; i < 4; i++) {
                uint2 hv, lv; bf16_split4(rxa[i], hv, lv);
                int off = ar[i] * PSTRB + ac[i];
                *(uint2*)(base + AH_OFF + off) = hv;
                *(uint2*)(base + AL_OFF + off) = lv;
            }
#pragma unroll
            for (int i = 0; i < 6; i++) {
                uint2 hv, lv; bf16_split4(rxb[i], hv, lv);
                int off = wr[i] * PSTRB + wc[i];
                *(uint2*)(base + BH_OFF + off) = hv;
                *(uint2*)(base + BL_OFF + off) = lv;
            }
        }
        __syncthreads();
    }

    // epilogue: fragment -> direct global stores (pairs stay in one section)
    const int erow = lane >> 2;          // 0..7
    const int ecol = (lane & 3) * 2;     // 0,2,4,6
#pragma unroll
    for (int mi = 0; mi < 2; mi++) {
        const int rg = row0 + warp_m + mi * 16 + erow;
#pragma unroll
        for (int nj = 0; nj < 12; nj++) {
            const int n = warp_n + nj * 8 + ecol;
            const int s = n >> 6;
            const int h = n & 63;
            float* op = (s == 0) ? g_k : (s == 1) ? g_q : g_v;
            *(float2*)&op[(size_t)rg * H_ + h] =
                make_float2(acc[mi][nj][0], acc[mi][nj][1]);
            *(float2*)&op[(size_t)(rg + 8) * H_ + h] =
                make_float2(acc[mi][nj][2], acc[mi][nj][3]);
        }
    }
}

// ---------------------------------------------------------------------------
// One-shot transpose of g_k [b][t][h] -> g_kt [b][h][t]
// ---------------------------------------------------------------------------
__global__ void ktrans_kernel()
{
    __shared__ float tile[32][33];
    const int b = blockIdx.z, h0 = blockIdx.y * 32, t0 = blockIdx.x * 32;
    const float* src = g_k + (size_t)b * T_ * H_;
    float* dst = g_kt + (size_t)b * H_ * T_;
    tile[threadIdx.y][threadIdx.x] =
        src[(size_t)(t0 + threadIdx.y) * H_ + h0 + threadIdx.x];
    __syncthreads();
    dst[(size_t)(h0 + threadIdx.y) * T_ + t0 + threadIdx.x] =
        tile[threadIdx.x][threadIdx.y];
}

// ---------------------------------------------------------------------------
// Flash attention (fp32, causal, scale pre-folded). BM=BN=64.
// K tile held TRANSPOSED in smem (kt[d][key]) -> conflict-free QK^T loads.
// Double-buffered KV smem pipeline; paired q-tiles (j, 31-j) for balance.
// ---------------------------------------------------------------------------
#define BM 64
#define BN 64
#define SSTR 68
#define KSTR 68

#define ATTN_SMEM ((2 * BM * SSTR + 4 * BN * KSTR) * 4)

__global__ __launch_bounds__(256, 1)
void attn_kernel(float* __restrict__ out)
{
    extern __shared__ float sm[];
    float* qs  = sm;
    float* ps  = qs + BM * SSTR;
    float* ktb = ps + BM * SSTR;
    float* vsb = ktb + 2 * BN * KSTR;

    const int tid = threadIdx.x;
    const int ty = tid >> 4;
    const int tx = tid & 15;
    const int b  = blockIdx.y;

    const float* qg  = g_q  + (size_t)b * T_ * H_;
    const float* ktg = g_kt + (size_t)b * H_ * T_;
    const float* vg  = g_v  + (size_t)b * T_ * H_;

    int lr[4], lc[4];
#pragma unroll
    for (int i = 0; i < 4; i++) {
        int idx = tid + i * 256;
        lr[i] = idx >> 4;
        lc[i] = (idx & 15) << 2;
    }

    const int NQB = T_ / BM;   // 32

#pragma unroll 1
    for (int pass = 0; pass < 2; pass++) {
        const int qb = pass ? (NQB - 1 - (int)blockIdx.x) : (int)blockIdx.x;
        const int q0 = qb * BM;
        const int ntiles = qb + 1;

        __syncthreads();
#pragma unroll
        for (int i = 0; i < 4; i++)
            *(float4*)&qs[lr[i] * SSTR + lc[i]] =
                *(const float4*)(qg + (size_t)(q0 + lr[i]) * H_ + lc[i]);

        {
            float4 rk[4], rv[4];
#pragma unroll
            for (int i = 0; i < 4; i++) {
                rk[i] = *(const float4*)(ktg + (size_t)lr[i] * T_ + lc[i]);
                rv[i] = *(const float4*)(vg  + (size_t)lr[i] * H_ + lc[i]);
            }
#pragma unroll
            for (int i = 0; i < 4; i++) {
                *(float4*)&ktb[lr[i] * KSTR + lc[i]] = rk[i];
                *(float4*)&vsb[lr[i] * KSTR + lc[i]] = rv[i];
            }
        }

        float m[4], l[4], o[4][4];
#pragma unroll
        for (int i = 0; i < 4; i++) {
            m[i] = -1e30f; l[i] = 0.f;
#pragma unroll
            for (int j = 0; j < 4; j++) o[i][j] = 0.f;
        }

        __syncthreads();

        for (int kb = 0; kb < ntiles; kb++) {
            const int cur = kb & 1;
            const int key0 = kb * BN;
            float* kt = ktb + cur * BN * KSTR;
            float* vs = vsb + cur * BN * KSTR;

            float4 rk[4], rv[4];
            const bool more = (kb + 1 < ntiles);
            if (more) {
                const int nkey0 = key0 + BN;
#pragma unroll
                for (int i = 0; i < 4; i++) {
                    rk[i] = *(const float4*)(ktg + (size_t)lr[i] * T_ + nkey0 + lc[i]);
                    rv[i] = *(const float4*)(vg + (size_t)(nkey0 + lr[i]) * H_ + lc[i]);
                }
            }

            float s[4][4];
#pragma unroll
            for (int i = 0; i < 4; i++)
#pragma unroll
                for (int j = 0; j < 4; j++) s[i][j] = 0.f;

#pragma unroll
            for (int d = 0; d < H_; d += 4) {
                float4 a[4];
#pragma unroll
                for (int i = 0; i < 4; i++)
                    a[i] = *(float4*)&qs[(ty * 4 + i) * SSTR + d];
                float4 b0 = *(float4*)&kt[(d + 0) * KSTR + tx * 4];
                float4 b1 = *(float4*)&kt[(d + 1) * KSTR + tx * 4];
                float4 b2 = *(float4*)&kt[(d + 2) * KSTR + tx * 4];
                float4 b3 = *(float4*)&kt[(d + 3) * KSTR + tx * 4];
#pragma unroll
                for (int i = 0; i < 4; i++) {
                    s[i][0] += a[i].x * b0.x + a[i].y * b1.x +
                               a[i].z * b2.x + a[i].w * b3.x;
                    s[i][1] += a[i].x * b0.y + a[i].y * b1.y +
                               a[i].z * b2.y + a[i].w * b3.y;
                    s[i][2] += a[i].x * b0.z + a[i].y * b1.z +
                               a[i].z * b2.z + a[i].w * b3.z;
                    s[i][3] += a[i].x * b0.w + a[i].y * b1.w +
                               a[i].z * b2.w + a[i].w * b3.w;
                }
            }

            if (kb == qb) {
#pragma unroll
                for (int i = 0; i < 4; i++)
#pragma unroll
                    for (int j = 0; j < 4; j++)
                        if (key0 + tx * 4 + j > q0 + ty * 4 + i)
                            s[i][j] = -1e30f;
            }

#pragma unroll
            for (int i = 0; i < 4; i++) {
                float mx = fmaxf(fmaxf(s[i][0], s[i][1]),
                                 fmaxf(s[i][2], s[i][3]));
#pragma unroll
                for (int off = 8; off >= 1; off >>= 1)
                    mx = fmaxf(mx, __shfl_xor_sync(0xffffffffu, mx, off));
                float mn = fmaxf(m[i], mx);
                float corr = __expf(m[i] - mn);
                float p0 = __expf(s[i][0] - mn);
                float p1 = __expf(s[i][1] - mn);
                float p2 = __expf(s[i][2] - mn);
                float p3 = __expf(s[i][3] - mn);
                float sum = p0 + p1 + p2 + p3;
#pragma unroll
                for (int off = 8; off >= 1; off >>= 1)
                    sum += __shfl_xor_sync(0xffffffffu, sum, off);
                l[i] = l[i] * corr + sum;
                m[i] = mn;
                o[i][0] *= corr; o[i][1] *= corr;
                o[i][2] *= corr; o[i][3] *= corr;
                *(float4*)&ps[(ty * 4 + i) * SSTR + tx * 4] =
                    make_float4(p0, p1, p2, p3);
            }
            __syncthreads();

#pragma unroll
            for (int s0 = 0; s0 < BN; s0 += 4) {
                float4 pa[4];
#pragma unroll
                for (int i = 0; i < 4; i++)
                    pa[i] = *(float4*)&ps[(ty * 4 + i) * SSTR + s0];
                float4 v0 = *(float4*)&vs[(s0 + 0) * KSTR + tx * 4];
                float4 v1 = *(float4*)&vs[(s0 + 1) * KSTR + tx * 4];
                float4 v2 = *(float4*)&vs[(s0 + 2) * KSTR + tx * 4];
                float4 v3 = *(float4*)&vs[(s0 + 3) * KSTR + tx * 4];
#pragma unroll
                for (int i = 0; i < 4; i++) {
                    o[i][0] += pa[i].x * v0.x + pa[i].y * v1.x +
                               pa[i].z * v2.x + pa[i].w * v3.x;
                    o[i][1] += pa[i].x * v0.y + pa[i].y * v1.y +
                               pa[i].z * v2.y + pa[i].w * v3.y;
                    o[i][2] += pa[i].x * v0.z + pa[i].y * v1.z +
                               pa[i].z * v2.z + pa[i].w * v3.z;
                    o[i][3] += pa[i].x * v0.w + pa[i].y * v1.w +
                               pa[i].z * v2.w + pa[i].w * v3.w;
                }
            }

            if (more) {
                float* ktn = ktb + (cur ^ 1) * BN * KSTR;
                float* vsn = vsb + (cur ^ 1) * BN * KSTR;
#pragma unroll
                for (int i = 0; i < 4; i++) {
                    *(float4*)&ktn[lr[i] * KSTR + lc[i]] = rk[i];
                    *(float4*)&vsn[lr[i] * KSTR + lc[i]] = rv[i];
                }
            }
            __syncthreads();
        }

#pragma unroll
        for (int i = 0; i < 4; i++) {
            float inv = 1.f / l[i];
            float4 v = make_float4(o[i][0] * inv, o[i][1] * inv,
                                   o[i][2] * inv, o[i][3] * inv);
            *(float4*)(out + ((size_t)b * T_ + q0 + ty * 4 + i) * H_ + tx * 4) = v;
        }
    }
}

// ---------------------------------------------------------------------------
extern "C" void kernel_launch(void* const* d_in, const int* in_sizes, int n_in,
                              void* d_out, int out_size)
{
    const float* x  = (const float*)d_in[0];
    const float* Wk = (const float*)d_in[1];
    const float* Wq = (const float*)d_in[2];
    const float* Wv = (const float*)d_in[3];
    float* out = (float*)d_out;

    (void)in_sizes; (void)n_in; (void)out_size;

    cudaFuncSetAttribute(proj_kernel,
                         cudaFuncAttributeMaxDynamicSharedMemorySize,
                         PROJ_SMEM);
    cudaFuncSetAttribute(attn_kernel,
                         cudaFuncAttributeMaxDynamicSharedMemorySize,
                         ATTN_SMEM);

    proj_kernel<<<(B_ * T_) / 128, 256, PROJ_SMEM>>>(x, Wk, Wq, Wv);

    dim3 kgrid(T_ / 32, H_ / 32, B_);
    ktrans_kernel<<<kgrid, dim3(32, 32)>>>();

    dim3 agrid((T_ / BM) / 2, B_);
    attn_kernel<<<agrid, 256, ATTN_SMEM>>>(out);
}

// round 15
// speedup vs baseline: 3.7197x; 1.6615x over previous
#include <cuda_runtime.h>
#include <cuda_bf16.h>
#include <math.h>
#include <stdint.h>

#define B_ 8
#define T_ 2048
#define C_ 1024
#define H_ 64

// Scratch (device globals: allocation-free)
__device__ float g_q[B_ * T_ * H_];     // 8*q (logit scale folded into Wq)
__device__ float g_k[B_ * T_ * H_];
__device__ float g_v[B_ * T_ * H_];

// ===========================================================================
// Warp-level tensor core helpers (sm_80+ features: compile for plain sm_103)
// ===========================================================================
__device__ __forceinline__ uint32_t smem_u32(const void* p) {
    uint32_t a;
    asm("{ .reg .u64 t; cvta.to.shared.u64 t, %1; cvt.u32.u64 %0, t; }"
        : "=r"(a) : "l"(p));
    return a;
}

#define LDSM4(r0, r1, r2, r3, addr) \
    asm volatile("ldmatrix.sync.aligned.m8n8.x4.shared.b16 {%0,%1,%2,%3}, [%4];" \
                 : "=r"(r0), "=r"(r1), "=r"(r2), "=r"(r3) : "r"(addr))
#define LDSM2(r0, r1, addr) \
    asm volatile("ldmatrix.sync.aligned.m8n8.x2.shared.b16 {%0,%1}, [%2];" \
                 : "=r"(r0), "=r"(r1) : "r"(addr))
#define LDSM2T(r0, r1, addr) \
    asm volatile("ldmatrix.sync.aligned.m8n8.x2.trans.shared.b16 {%0,%1}, [%2];" \
                 : "=r"(r0), "=r"(r1) : "r"(addr))

__device__ __forceinline__ void mma16816(float* c,
                                         uint32_t a0, uint32_t a1,
                                         uint32_t a2, uint32_t a3,
                                         uint32_t b0, uint32_t b1) {
    asm volatile(
        "mma.sync.aligned.m16n8k16.row.col.f32.bf16.bf16.f32 "
        "{%0,%1,%2,%3}, {%4,%5,%6,%7}, {%8,%9}, {%0,%1,%2,%3};"
        : "+f"(c[0]), "+f"(c[1]), "+f"(c[2]), "+f"(c[3])
        : "r"(a0), "r"(a1), "r"(a2), "r"(a3), "r"(b0), "r"(b1));
}

// split one float4 into hi/lo bf16x4 (packed as uint2 each)
__device__ __forceinline__ void bf16_split4(float4 v, uint2& hv, uint2& lv) {
    __nv_bfloat16 h0 = __float2bfloat16_rn(v.x);
    __nv_bfloat16 h1 = __float2bfloat16_rn(v.y);
    __nv_bfloat16 h2 = __float2bfloat16_rn(v.z);
    __nv_bfloat16 h3 = __float2bfloat16_rn(v.w);
    __nv_bfloat16 l0 = __float2bfloat16_rn(v.x - __bfloat162float(h0));
    __nv_bfloat16 l1 = __float2bfloat16_rn(v.y - __bfloat162float(h1));
    __nv_bfloat16 l2 = __float2bfloat16_rn(v.z - __bfloat162float(h2));
    __nv_bfloat16 l3 = __float2bfloat16_rn(v.w - __bfloat162float(h3));
    hv.x = (uint32_t)__bfloat16_as_ushort(h0) |
           ((uint32_t)__bfloat16_as_ushort(h1) << 16);
    hv.y = (uint32_t)__bfloat16_as_ushort(h2) |
           ((uint32_t)__bfloat16_as_ushort(h3) << 16);
    lv.x = (uint32_t)__bfloat16_as_ushort(l0) |
           ((uint32_t)__bfloat16_as_ushort(l1) << 16);
    lv.y = (uint32_t)__bfloat16_as_ushort(l2) |
           ((uint32_t)__bfloat16_as_ushort(l3) << 16);
}

// split two fp32 values into packed hi/lo bf16x2
__device__ __forceinline__ void packsplit2(float a, float b,
                                           uint32_t& h, uint32_t& l) {
    __nv_bfloat16 ha = __float2bfloat16_rn(a);
    __nv_bfloat16 hb = __float2bfloat16_rn(b);
    __nv_bfloat16 la = __float2bfloat16_rn(a - __bfloat162float(ha));
    __nv_bfloat16 lb = __float2bfloat16_rn(b - __bfloat162float(hb));
    h = (uint32_t)__bfloat16_as_ushort(ha) |
        ((uint32_t)__bfloat16_as_ushort(hb) << 16);
    l = (uint32_t)__bfloat16_as_ushort(la) |
        ((uint32_t)__bfloat16_as_ushort(lb) << 16);
}

// ---------------------------------------------------------------------------
// Tensor-core projection GEMM (mma.sync bf16 hi/lo split, 3 MMAs per pair):
//   out[m][h] = sum_c x[m][c] * W[h][c],  M=16384, N=192, K=1024.
// Block: 128 M x 192 N, 256 threads = 8 warps (4 x 2), warp tile 32 x 96.
// BK=32, double-buffered smem, 40-bf16 (80 B) row stride.
// ---------------------------------------------------------------------------
#define PSTRB 40
#define BUF_ELE (320 * PSTRB * 2)
#define AH_OFF 0
#define AL_OFF (128 * PSTRB)
#define BH_OFF (256 * PSTRB)
#define BL_OFF (448 * PSTRB)
#define PROJ_SMEM (2 * BUF_ELE * 2)

__global__ __launch_bounds__(256, 1)
void proj_kernel(const float* __restrict__ x,
                 const float* __restrict__ Wk,
                 const float* __restrict__ Wq,
                 const float* __restrict__ Wv)
{
    extern __shared__ __align__(16) char smem[];
    __nv_bfloat16* sb16 = (__nv_bfloat16*)smem;
    const uint32_t sb = smem_u32(smem);

    const int tid = threadIdx.x;
    const int wid = tid >> 5;
    const int lane = tid & 31;
    const int row0 = blockIdx.x * 128;
    const int warp_m = (wid >> 1) * 32;
    const int warp_n = (wid & 1) * 96;

    int ar[4], ac[4];
#pragma unroll
    for (int i = 0; i < 4; i++) {
        int idx = tid + i * 256;
        ar[i] = idx >> 3;
        ac[i] = (idx & 7) << 2;
    }
    const float* wp[6];
    float wsc[6];
    int wr[6], wc[6];
#pragma unroll
    for (int i = 0; i < 6; i++) {
        int idx = tid + i * 256;
        int r = idx >> 3;
        wr[i] = r;
        wc[i] = (idx & 7) << 2;
        if (r < 64)       { wp[i] = Wk + (size_t)r * C_;         wsc[i] = 1.f; }
        else if (r < 128) { wp[i] = Wq + (size_t)(r - 64) * C_;  wsc[i] = 8.f; }
        else              { wp[i] = Wv + (size_t)(r - 128) * C_; wsc[i] = 1.f; }
    }

    const uint32_t a_lrow = (uint32_t)(lane & 15);
    const uint32_t a_koff = (uint32_t)((lane >> 4) * 16);
    const uint32_t b_lrow = (uint32_t)(lane & 7);
    const uint32_t b_koff = (uint32_t)(((lane >> 3) & 1) * 16);

    float acc[2][12][4];
#pragma unroll
    for (int mi = 0; mi < 2; mi++)
#pragma unroll
        for (int nj = 0; nj < 12; nj++)
#pragma unroll
            for (int q = 0; q < 4; q++) acc[mi][nj][q] = 0.f;

    {
        __nv_bfloat16* base = sb16;
#pragma unroll
        for (int i = 0; i < 4; i++) {
            float4 v = *(const float4*)(x + (size_t)(row0 + ar[i]) * C_ + ac[i]);
            uint2 hv, lv; bf16_split4(v, hv, lv);
            int off = ar[i] * PSTRB + ac[i];
            *(uint2*)(base + AH_OFF + off) = hv;
            *(uint2*)(base + AL_OFF + off) = lv;
        }
#pragma unroll
        for (int i = 0; i < 6; i++) {
            float4 v = *(const float4*)(wp[i] + wc[i]);
            v.x *= wsc[i]; v.y *= wsc[i]; v.z *= wsc[i]; v.w *= wsc[i];
            uint2 hv, lv; bf16_split4(v, hv, lv);
            int off = wr[i] * PSTRB + wc[i];
            *(uint2*)(base + BH_OFF + off) = hv;
            *(uint2*)(base + BL_OFF + off) = lv;
        }
    }
    __syncthreads();

    const int NKT = C_ / 32;
    for (int kt = 0; kt < NKT; kt++) {
        const int cur = kt & 1;
        const bool more = (kt + 1 < NKT);

        float4 rxa[4], rxb[6];
        if (more) {
            const int kc = (kt + 1) * 32;
#pragma unroll
            for (int i = 0; i < 4; i++)
                rxa[i] = *(const float4*)(x + (size_t)(row0 + ar[i]) * C_ + kc + ac[i]);
#pragma unroll
            for (int i = 0; i < 6; i++) {
                float4 v = *(const float4*)(wp[i] + kc + wc[i]);
                v.x *= wsc[i]; v.y *= wsc[i]; v.z *= wsc[i]; v.w *= wsc[i];
                rxb[i] = v;
            }
        }

        const uint32_t bufb = sb + cur * BUF_ELE * 2;
#pragma unroll
        for (int ks = 0; ks < 2; ks++) {
            const uint32_t kb = ks * 32;
            uint32_t ah[2][4], al[2][4];
#pragma unroll
            for (int mi = 0; mi < 2; mi++) {
                uint32_t rowa = warp_m + mi * 16 + a_lrow;
                uint32_t aaddr = bufb + AH_OFF * 2 + rowa * (PSTRB * 2) +
                                 a_koff + kb;
                LDSM4(ah[mi][0], ah[mi][1], ah[mi][2], ah[mi][3], aaddr);
                uint32_t laddr = aaddr + (AL_OFF - AH_OFF) * 2;
                LDSM4(al[mi][0], al[mi][1], al[mi][2], al[mi][3], laddr);
            }
#pragma unroll
            for (int nj = 0; nj < 12; nj++) {
                uint32_t rowb = warp_n + nj * 8 + b_lrow;
                uint32_t baddr = bufb + BH_OFF * 2 + rowb * (PSTRB * 2) +
                                 b_koff + kb;
                uint32_t bh0, bh1, bl0, bl1;
                LDSM2(bh0, bh1, baddr);
                LDSM2(bl0, bl1, baddr + (BL_OFF - BH_OFF) * 2);
#pragma unroll
                for (int mi = 0; mi < 2; mi++) {
                    mma16816(acc[mi][nj], ah[mi][0], ah[mi][1], ah[mi][2],
                             ah[mi][3], bh0, bh1);
                    mma16816(acc[mi][nj], ah[mi][0], ah[mi][1], ah[mi][2],
                             ah[mi][3], bl0, bl1);
                    mma16816(acc[mi][nj], al[mi][0], al[mi][1], al[mi][2],
                             al[mi][3], bh0, bh1);
                }
            }
        }

        if (more) {
            __nv_bfloat16* base = sb16 + (cur ^ 1) * BUF_ELE;
#pragma unroll
            for (int i = 0; i < 4; i++) {
                uint2 hv, lv; bf16_split4(rxa[i], hv, lv);
                int off = ar[i] * PSTRB + ac[i];
                *(uint2*)(base + AH_OFF + off) = hv;
                *(uint2*)(base + AL_OFF + off) = lv;
            }
#pragma unroll
            for (int i = 0; i < 6; i++) {
                uint2 hv, lv; bf16_split4(rxb[i], hv, lv);
                int off = wr[i] * PSTRB + wc[i];
                *(uint2*)(base + BH_OFF + off) = hv;
                *(uint2*)(base + BL_OFF + off) = lv;
            }
        }
        __syncthreads();
    }

    const int erow = lane >> 2;
    const int ecol = (lane & 3) * 2;
#pragma unroll
    for (int mi = 0; mi < 2; mi++) {
        const int rg = row0 + warp_m + mi * 16 + erow;
#pragma unroll
        for (int nj = 0; nj < 12; nj++) {
            const int n = warp_n + nj * 8 + ecol;
            const int s = n >> 6;
            const int h = n & 63;
            float* op = (s == 0) ? g_k : (s == 1) ? g_q : g_v;
            *(float2*)&op[(size_t)rg * H_ + h] =
                make_float2(acc[mi][nj][0], acc[mi][nj][1]);
            *(float2*)&op[(size_t)(rg + 8) * H_ + h] =
                make_float2(acc[mi][nj][2], acc[mi][nj][3]);
        }
    }
}

// ---------------------------------------------------------------------------
// Tensor-core flash attention (mma.sync, bf16 hi/lo split, causal).
// BM=64 q rows, BN=64 keys/tile. 256 threads:
//   warps 0-3 = consumers (m16 each; QK^T + softmax + PV, P in registers)
//   warps 4-7 = producers (LDG fp32 -> split bf16 -> STS, double-buffered KV)
// Paired q-tiles (j, 31-j): 33 equal tiles per block, 128 blocks (16x8).
// Row stride 72 bf16 (144 B): conflict-free ldmatrix.
// ---------------------------------------------------------------------------
// byte offsets into dynamic smem
#define AQH 0
#define AQL 9216
#define ABUF 18432            // two KV buffers follow
#define AKH 0
#define AKL 9216
#define AVH 18432
#define AVL 27648
#define ABUFSZ 36864
#define ASTR 72               // row stride in bf16
#define AROWB 144             // row stride in bytes
#define ATTN_SMEM (ABUF + 2 * ABUFSZ)   // 92160 bytes

__global__ __launch_bounds__(256, 1)
void attn_kernel(float* __restrict__ out)
{
    extern __shared__ __align__(16) char smem[];
    __nv_bfloat16* s16 = (__nv_bfloat16*)smem;
    const uint32_t sb = smem_u32(smem);

    const int tid = threadIdx.x;
    const int wid = tid >> 5;
    const int lane = tid & 31;
    const int b = blockIdx.y;

    const float* qg = g_q + (size_t)b * T_ * H_;
    const float* kg = g_k + (size_t)b * T_ * H_;
    const float* vg = g_v + (size_t)b * T_ * H_;

    // producer load slots (threads 128..255): 64 rows x 64 cols fp32 per tile
    const int pt = tid & 127;
    int prow[8], pcol[8];
#pragma unroll
    for (int i = 0; i < 8; i++) {
        int idx = pt + i * 128;
        prow[i] = idx >> 4;
        pcol[i] = (idx & 15) << 2;
    }

    // consumer constants
    const int warp_m = wid * 16;
    const uint32_t a_lrow = (uint32_t)(lane & 15);
    const uint32_t a_koff = (uint32_t)((lane >> 4) * 16);
    const uint32_t b_lrow = (uint32_t)(lane & 7);
    const uint32_t b_koff = (uint32_t)(((lane >> 3) & 1) * 16);
    const int qrow = lane >> 2;        // local row within m16 (and +8)
    const int qcol = (lane & 3) * 2;   // local col pair base

#pragma unroll 1
    for (int pass = 0; pass < 2; pass++) {
        const int qb = pass ? (31 - (int)blockIdx.x) : (int)blockIdx.x;
        const int q0 = qb * 64;
        const int ntiles = qb + 1;

        __syncthreads();   // previous pass fully consumed before Q/KV0 overwrite

        if (wid >= 4) {
            // Q tile (holds 8*q already)
#pragma unroll
            for (int i = 0; i < 8; i++) {
                float4 v = *(const float4*)(qg + (size_t)(q0 + prow[i]) * H_ + pcol[i]);
                uint2 hv, lv; bf16_split4(v, hv, lv);
                int off = prow[i] * ASTR + pcol[i];
                *(uint2*)(s16 + (AQH >> 1) + off) = hv;
                *(uint2*)(s16 + (AQL >> 1) + off) = lv;
            }
            // KV tile 0 -> buffer 0
            __nv_bfloat16* kb0 = s16 + (ABUF >> 1);
#pragma unroll
            for (int i = 0; i < 8; i++) {
                int off = prow[i] * ASTR + pcol[i];
                float4 v = *(const float4*)(kg + (size_t)prow[i] * H_ + pcol[i]);
                uint2 hv, lv; bf16_split4(v, hv, lv);
                *(uint2*)(kb0 + (AKH >> 1) + off) = hv;
                *(uint2*)(kb0 + (AKL >> 1) + off) = lv;
                float4 w = *(const float4*)(vg + (size_t)prow[i] * H_ + pcol[i]);
                bf16_split4(w, hv, lv);
                *(uint2*)(kb0 + (AVH >> 1) + off) = hv;
                *(uint2*)(kb0 + (AVL >> 1) + off) = lv;
            }
        }

        float m0 = -1e30f, m1 = -1e30f, l0 = 0.f, l1 = 0.f;
        float o[8][4];
#pragma unroll
        for (int dj = 0; dj < 8; dj++)
#pragma unroll
            for (int q = 0; q < 4; q++) o[dj][q] = 0.f;

        __syncthreads();   // Q + KV0 ready

        for (int kb = 0; kb < ntiles; kb++) {
            const int cur = kb & 1;
            const int key0 = kb * 64;

            if (wid >= 4) {
                // produce next KV tile into the other buffer
                if (kb + 1 < ntiles) {
                    const int nk0 = key0 + 64;
                    __nv_bfloat16* bufn = s16 + ((ABUF + ((kb + 1) & 1) * ABUFSZ) >> 1);
#pragma unroll
                    for (int i = 0; i < 8; i++) {
                        int off = prow[i] * ASTR + pcol[i];
                        float4 v = *(const float4*)(kg + (size_t)(nk0 + prow[i]) * H_ + pcol[i]);
                        uint2 hv, lv; bf16_split4(v, hv, lv);
                        *(uint2*)(bufn + (AKH >> 1) + off) = hv;
                        *(uint2*)(bufn + (AKL >> 1) + off) = lv;
                        float4 w = *(const float4*)(vg + (size_t)(nk0 + prow[i]) * H_ + pcol[i]);
                        bf16_split4(w, hv, lv);
                        *(uint2*)(bufn + (AVH >> 1) + off) = hv;
                        *(uint2*)(bufn + (AVL >> 1) + off) = lv;
                    }
                }
            } else {
                const uint32_t bufb = sb + ABUF + cur * ABUFSZ;

                // ---- S = Q @ K^T (hi/lo split: QhKh + QhKl + QlKh) ----
                float c[8][4];
#pragma unroll
                for (int nj = 0; nj < 8; nj++)
#pragma unroll
                    for (int q = 0; q < 4; q++) c[nj][q] = 0.f;

#pragma unroll
                for (int kk = 0; kk < 4; kk++) {
                    uint32_t qaddr = sb + AQH + (warp_m + a_lrow) * AROWB +
                                     a_koff + kk * 32;
                    uint32_t qh[4], ql[4];
                    LDSM4(qh[0], qh[1], qh[2], qh[3], qaddr);
                    LDSM4(ql[0], ql[1], ql[2], ql[3], qaddr + (AQL - AQH));
#pragma unroll
                    for (int nj = 0; nj < 8; nj++) {
                        uint32_t kaddr = bufb + AKH + (nj * 8 + b_lrow) * AROWB +
                                         b_koff + kk * 32;
                        uint32_t kh0, kh1, kl0, kl1;
                        LDSM2(kh0, kh1, kaddr);
                        LDSM2(kl0, kl1, kaddr + (AKL - AKH));
                        mma16816(c[nj], qh[0], qh[1], qh[2], qh[3], kh0, kh1);
                        mma16816(c[nj], qh[0], qh[1], qh[2], qh[3], kl0, kl1);
                        mma16816(c[nj], ql[0], ql[1], ql[2], ql[3], kh0, kh1);
                    }
                }

                // ---- causal mask (diagonal tile only) ----
                if (kb == qb) {
                    const int r0 = q0 + warp_m + qrow;
                    const int n0 = key0 + qcol;
#pragma unroll
                    for (int nj = 0; nj < 8; nj++) {
                        int n = n0 + nj * 8;
                        if (n     > r0)     c[nj][0] = -1e30f;
                        if (n + 1 > r0)     c[nj][1] = -1e30f;
                        if (n     > r0 + 8) c[nj][2] = -1e30f;
                        if (n + 1 > r0 + 8) c[nj][3] = -1e30f;
                    }
                }

                // ---- online softmax (rows r and r+8; quad reductions) ----
                float mx0 = -1e30f, mx1 = -1e30f;
#pragma unroll
                for (int nj = 0; nj < 8; nj++) {
                    mx0 = fmaxf(mx0, fmaxf(c[nj][0], c[nj][1]));
                    mx1 = fmaxf(mx1, fmaxf(c[nj][2], c[nj][3]));
                }
                mx0 = fmaxf(mx0, __shfl_xor_sync(0xffffffffu, mx0, 1));
                mx0 = fmaxf(mx0, __shfl_xor_sync(0xffffffffu, mx0, 2));
                mx1 = fmaxf(mx1, __shfl_xor_sync(0xffffffffu, mx1, 1));
                mx1 = fmaxf(mx1, __shfl_xor_sync(0xffffffffu, mx1, 2));
                float mn0 = fmaxf(m0, mx0), mn1 = fmaxf(m1, mx1);
                float corr0 = __expf(m0 - mn0), corr1 = __expf(m1 - mn1);
                m0 = mn0; m1 = mn1;

                float sum0 = 0.f, sum1 = 0.f;
#pragma unroll
                for (int nj = 0; nj < 8; nj++) {
                    c[nj][0] = __expf(c[nj][0] - mn0); sum0 += c[nj][0];
                    c[nj][1] = __expf(c[nj][1] - mn0); sum0 += c[nj][1];
                    c[nj][2] = __expf(c[nj][2] - mn1); sum1 += c[nj][2];
                    c[nj][3] = __expf(c[nj][3] - mn1); sum1 += c[nj][3];
                }
                sum0 += __shfl_xor_sync(0xffffffffu, sum0, 1);
                sum0 += __shfl_xor_sync(0xffffffffu, sum0, 2);
                sum1 += __shfl_xor_sync(0xffffffffu, sum1, 1);
                sum1 += __shfl_xor_sync(0xffffffffu, sum1, 2);
                l0 = l0 * corr0 + sum0;
                l1 = l1 * corr1 + sum1;
#pragma unroll
                for (int dj = 0; dj < 8; dj++) {
                    o[dj][0] *= corr0; o[dj][1] *= corr0;
                    o[dj][2] *= corr1; o[dj][3] *= corr1;
                }

                // ---- pack P (C-frag -> A-frag, hi/lo) ----
                uint32_t ph[4][4], pl[4][4];
#pragma unroll
                for (int kk = 0; kk < 4; kk++) {
                    packsplit2(c[2 * kk][0],     c[2 * kk][1],     ph[kk][0], pl[kk][0]);
                    packsplit2(c[2 * kk][2],     c[2 * kk][3],     ph[kk][1], pl[kk][1]);
                    packsplit2(c[2 * kk + 1][0], c[2 * kk + 1][1], ph[kk][2], pl[kk][2]);
                    packsplit2(c[2 * kk + 1][2], c[2 * kk + 1][3], ph[kk][3], pl[kk][3]);
                }

                // ---- O += P @ V (V via ldmatrix.trans; PhVh + PhVl + PlVh) ----
#pragma unroll
                for (int kk = 0; kk < 4; kk++) {
                    uint32_t vrow = kk * 16 + ((lane >> 3) & 1) * 8 + (lane & 7);
                    uint32_t vbase = bufb + AVH + vrow * AROWB;
#pragma unroll
                    for (int dj = 0; dj < 8; dj++) {
                        uint32_t vaddr = vbase + dj * 16;
                        uint32_t vh0, vh1, vl0, vl1;
                        LDSM2T(vh0, vh1, vaddr);
                        LDSM2T(vl0, vl1, vaddr + (AVL - AVH));
                        mma16816(o[dj], ph[kk][0], ph[kk][1], ph[kk][2],
                                 ph[kk][3], vh0, vh1);
                        mma16816(o[dj], ph[kk][0], ph[kk][1], ph[kk][2],
                                 ph[kk][3], vl0, vl1);
                        mma16816(o[dj], pl[kk][0], pl[kk][1], pl[kk][2],
                                 pl[kk][3], vh0, vh1);
                    }
                }
            }
            __syncthreads();   // buffer handoff
        }

        // ---- epilogue (consumers) ----
        if (wid < 4) {
            const int r0 = q0 + warp_m + qrow;
            const float inv0 = 1.f / l0, inv1 = 1.f / l1;
#pragma unroll
            for (int dj = 0; dj < 8; dj++) {
                const int d = dj * 8 + qcol;
                *(float2*)&out[((size_t)b * T_ + r0) * H_ + d] =
                    make_float2(o[dj][0] * inv0, o[dj][1] * inv0);
                *(float2*)&out[((size_t)b * T_ + r0 + 8) * H_ + d] =
                    make_float2(o[dj][2] * inv1, o[dj][3] * inv1);
            }
        }
    }
}

// ---------------------------------------------------------------------------
extern "C" void kernel_launch(void* const* d_in, const int* in_sizes, int n_in,
                              void* d_out, int out_size)
{
    const float* x  = (const float*)d_in[0];
    const float* Wk = (const float*)d_in[1];
    const float* Wq = (const float*)d_in[2];
    const float* Wv = (const float*)d_in[3];
    float* out = (float*)d_out;

    (void)in_sizes; (void)n_in; (void)out_size;

    cudaFuncSetAttribute(proj_kernel,
                         cudaFuncAttributeMaxDynamicSharedMemorySize,
                         PROJ_SMEM);
    cudaFuncSetAttribute(attn_kernel,
                         cudaFuncAttributeMaxDynamicSharedMemorySize,
                         ATTN_SMEM);

    proj_kernel<<<(B_ * T_) / 128, 256, PROJ_SMEM>>>(x, Wk, Wq, Wv);

    dim3 agrid(16, B_);
    attn_kernel<<<agrid, 256, ATTN_SMEM>>>(out);
}